// round 1
// baseline (speedup 1.0000x reference)
#include <cuda_runtime.h>
#include <math.h>

// Problem constants
#define NROWS_TOTAL 253952   // B*S*N = 16*512*31
#define D        256
#define V        64
#define NNODES   31
#define ROWS     64          // rows per CTA tile (253952 / 64 = 3968 CTAs exactly)
#define PITCH    260         // row pitch (floats) for activation buffers
#define WCP      68          // row pitch (floats) for weight chunk buffer
#define NTHREADS 256
#define GRID     (NROWS_TOTAL / ROWS)

// smem: X[64][260] + Y[64][260] + Wc[256][68] + ln_g[256] + ln_b[256]
#define SMEM_FLOATS (2 * ROWS * PITCH + D * WCP + 2 * D)
#define SMEM_BYTES  (SMEM_FLOATS * 4)

__device__ __forceinline__ float gelu_exact(float x) {
    // torch-default exact GELU: 0.5*x*(1+erf(x/sqrt(2)))
    return 0.5f * x * (1.0f + erff(x * 0.70710678118654752f));
}

// ---------------------------------------------------------------------------
// Gather: X[r][:] = emb[feat_idx[gr0 + r]][:]
// ---------------------------------------------------------------------------
__device__ __forceinline__ void gather_stage(
    float* __restrict__ X,
    const int* __restrict__ fidx,
    const float* __restrict__ emb,
    int gr0, int tid)
{
    for (int q = tid; q < ROWS * 64; q += NTHREADS) {   // 64 float4 per row
        int r  = q >> 6;
        int c4 = q & 63;
        int e  = __ldg(fidx + gr0 + r);
        float4 v = *(const float4*)(emb + (size_t)e * D + (c4 << 2));
        *(float4*)(X + r * PITCH + (c4 << 2)) = v;
    }
}

// ---------------------------------------------------------------------------
// GEMM stage: Out[r][j] = epi( sum_k In[r][k] * Wg[k][j] )
//   EPI = 0 : plain (no bias)                      -> logits
//   EPI = 1 : gelu(acc + bias)                     -> mlp layers
//   EPI = 2 : gelu(acc + bias) + memory residual   -> feats layer
// NCOLS is the weight leading dim / output width (256 or 64).
// Processes output columns in chunks of 64 staged through smem Wc.
// ---------------------------------------------------------------------------
template<int EPI, int NCOLS>
__device__ __forceinline__ void gemm_stage(
    const float* __restrict__ In,
    float* __restrict__ Out,
    float* __restrict__ Wc,
    const float* __restrict__ Wg,
    const float* __restrict__ bias,
    const float* __restrict__ memg,
    int gr0, int tid)
{
    const int tx = tid & 15;    // 16 column-groups of 4 -> 64 cols
    const int ty = tid >> 4;    // 16 row-groups; rows ty, ty+16, ty+32, ty+48

    for (int j0 = 0; j0 < NCOLS; j0 += 64) {
        __syncthreads();  // previous chunk compute (or previous stage) done
        // stage Wg[:, j0:j0+64] into smem
        #pragma unroll
        for (int q = tid; q < D * 16; q += NTHREADS) {  // 4096 float4
            int k  = q >> 4;
            int c4 = q & 15;
            float4 v = *(const float4*)(Wg + (size_t)k * NCOLS + j0 + (c4 << 2));
            *(float4*)(Wc + k * WCP + (c4 << 2)) = v;
        }
        __syncthreads();

        float acc[4][4] = {};
        #pragma unroll 4
        for (int k = 0; k < D; k += 4) {
            const float4 b0 = *(const float4*)(Wc + (k + 0) * WCP + (tx << 2));
            const float4 b1 = *(const float4*)(Wc + (k + 1) * WCP + (tx << 2));
            const float4 b2 = *(const float4*)(Wc + (k + 2) * WCP + (tx << 2));
            const float4 b3 = *(const float4*)(Wc + (k + 3) * WCP + (tx << 2));
            #pragma unroll
            for (int i = 0; i < 4; i++) {
                const float4 a = *(const float4*)(In + (ty + (i << 4)) * PITCH + k);
                acc[i][0] = fmaf(a.w, b3.x, fmaf(a.z, b2.x, fmaf(a.y, b1.x, fmaf(a.x, b0.x, acc[i][0]))));
                acc[i][1] = fmaf(a.w, b3.y, fmaf(a.z, b2.y, fmaf(a.y, b1.y, fmaf(a.x, b0.y, acc[i][1]))));
                acc[i][2] = fmaf(a.w, b3.z, fmaf(a.z, b2.z, fmaf(a.y, b1.z, fmaf(a.x, b0.z, acc[i][2]))));
                acc[i][3] = fmaf(a.w, b3.w, fmaf(a.z, b2.w, fmaf(a.y, b1.w, fmaf(a.x, b0.w, acc[i][3]))));
            }
        }

        // epilogue + store
        #pragma unroll
        for (int i = 0; i < 4; i++) {
            const int r = ty + (i << 4);
            float4 o;
            float* po = &o.x;
            #pragma unroll
            for (int jj = 0; jj < 4; jj++) {
                float v = acc[i][jj];
                if (EPI >= 1) v = gelu_exact(v + __ldg(bias + j0 + (tx << 2) + jj));
                po[jj] = v;
            }
            if (EPI == 2) {
                const float* mrow = memg + (size_t)((gr0 + r) / NNODES) * D + j0 + (tx << 2);
                o.x += __ldg(mrow + 0);
                o.y += __ldg(mrow + 1);
                o.z += __ldg(mrow + 2);
                o.w += __ldg(mrow + 3);
            }
            *(float4*)(Out + r * PITCH + j0 + (tx << 2)) = o;
        }
    }
}

// ---------------------------------------------------------------------------
// LayerNorm: Out[r][:] = (In[r][:] - mu)*rsqrt(var+1e-5)*g + b
// One warp per row, 8 rows in flight.
// ---------------------------------------------------------------------------
__device__ __forceinline__ void ln_stage(
    const float* __restrict__ In,
    float* __restrict__ Out,
    const float* __restrict__ sg,
    const float* __restrict__ sb,
    int tid)
{
    const int warp = tid >> 5;
    const int lane = tid & 31;
    for (int r = warp; r < ROWS; r += 8) {
        const float* row = In + r * PITCH;
        const float4 u = *(const float4*)(row + (lane << 2));
        const float4 w = *(const float4*)(row + 128 + (lane << 2));
        float s  = (u.x + u.y) + (u.z + u.w) + (w.x + w.y) + (w.z + w.w);
        float s2 = u.x*u.x + u.y*u.y + u.z*u.z + u.w*u.w
                 + w.x*w.x + w.y*w.y + w.z*w.z + w.w*w.w;
        #pragma unroll
        for (int off = 16; off > 0; off >>= 1) {
            s  += __shfl_xor_sync(0xffffffffu, s,  off);
            s2 += __shfl_xor_sync(0xffffffffu, s2, off);
        }
        const float mu  = s * (1.0f / 256.0f);
        const float var = s2 * (1.0f / 256.0f) - mu * mu;
        const float rs  = rsqrtf(var + 1e-5f);

        float* orow = Out + r * PITCH;
        int c = lane << 2;
        {
            const float4 g = *(const float4*)(sg + c);
            const float4 b = *(const float4*)(sb + c);
            float4 o;
            o.x = (u.x - mu) * rs * g.x + b.x;
            o.y = (u.y - mu) * rs * g.y + b.y;
            o.z = (u.z - mu) * rs * g.z + b.z;
            o.w = (u.w - mu) * rs * g.w + b.w;
            *(float4*)(orow + c) = o;
        }
        c = 128 + (lane << 2);
        {
            const float4 g = *(const float4*)(sg + c);
            const float4 b = *(const float4*)(sb + c);
            float4 o;
            o.x = (w.x - mu) * rs * g.x + b.x;
            o.y = (w.y - mu) * rs * g.y + b.y;
            o.z = (w.z - mu) * rs * g.z + b.z;
            o.w = (w.w - mu) * rs * g.w + b.w;
            *(float4*)(orow + c) = o;
        }
    }
}

// ---------------------------------------------------------------------------
// Softmax over V=64 logits per row; write to global output.
// ---------------------------------------------------------------------------
__device__ __forceinline__ void softmax_stage(
    const float* __restrict__ In,
    float* __restrict__ out,
    int gr0, int tid)
{
    const int warp = tid >> 5;
    const int lane = tid & 31;
    for (int r = warp; r < ROWS; r += 8) {
        const float* row = In + r * PITCH;
        const float v0 = row[lane];
        const float v1 = row[32 + lane];
        float m = fmaxf(v0, v1);
        #pragma unroll
        for (int off = 16; off > 0; off >>= 1)
            m = fmaxf(m, __shfl_xor_sync(0xffffffffu, m, off));
        const float e0 = expf(v0 - m);
        const float e1 = expf(v1 - m);
        float s = e0 + e1;
        #pragma unroll
        for (int off = 16; off > 0; off >>= 1)
            s += __shfl_xor_sync(0xffffffffu, s, off);
        const float inv = 1.0f / s;
        float* orow = out + (size_t)(gr0 + r) * V;
        orow[lane]      = e0 * inv;
        orow[32 + lane] = e1 * inv;
    }
}

// ---------------------------------------------------------------------------
// Main fused kernel: one CTA = 64 rows through the whole decoder head.
// ---------------------------------------------------------------------------
__global__ void __launch_bounds__(NTHREADS, 1)
decoder_kernel(const float* __restrict__ memory,
               const int*   __restrict__ feat_idx,
               const float* __restrict__ emb,
               const float* __restrict__ Wf, const float* __restrict__ bf,
               const float* __restrict__ lg, const float* __restrict__ lb,
               const float* __restrict__ W1, const float* __restrict__ b1,
               const float* __restrict__ W2, const float* __restrict__ b2,
               const float* __restrict__ Wo,
               float* __restrict__ out)
{
    extern __shared__ float sm[];
    float* X  = sm;
    float* Y  = X + ROWS * PITCH;
    float* Wc = Y + ROWS * PITCH;
    float* sg = Wc + D * WCP;
    float* sb = sg + D;

    const int tid = threadIdx.x;
    const int gr0 = blockIdx.x * ROWS;

    // preload LN params
    for (int i = tid; i < D; i += NTHREADS) { sg[i] = lg[i]; sb[i] = lb[i]; }

    // X = emb[feat_idx]
    gather_stage(X, feat_idx, emb, gr0, tid);
    // (gemm_stage opens with __syncthreads(), covering gather + LN-param writes)

    // Y = gelu(X @ Wf + bf) + memory
    gemm_stage<2, D>(X, Y, Wc, Wf, bf, memory, gr0, tid);
    __syncthreads();

    // X = LN(Y)
    ln_stage(Y, X, sg, sb, tid);

    // Y = gelu(X @ W1 + b1)
    gemm_stage<1, D>(X, Y, Wc, W1, b1, nullptr, gr0, tid);
    __syncthreads();

    // X = LN(Y)
    ln_stage(Y, X, sg, sb, tid);

    // Y = gelu(X @ W2 + b2)
    gemm_stage<1, D>(X, Y, Wc, W2, b2, nullptr, gr0, tid);
    // X[:, 0:64] = Y @ Wo   (gemm opens with syncthreads)
    gemm_stage<0, V>(Y, X, Wc, Wo, nullptr, nullptr, gr0, tid);
    __syncthreads();

    // out = softmax(X[:, 0:64])
    softmax_stage(X, out, gr0, tid);
}

// ---------------------------------------------------------------------------
// Harness entry
// ---------------------------------------------------------------------------
extern "C" void kernel_launch(void* const* d_in, const int* in_sizes, int n_in,
                              void* d_out, int out_size)
{
    const float* memory   = (const float*)d_in[0];
    const int*   feat_idx = (const int*)  d_in[1];
    const float* emb      = (const float*)d_in[2];
    const float* Wf       = (const float*)d_in[3];
    const float* bf       = (const float*)d_in[4];
    const float* lg       = (const float*)d_in[5];
    const float* lb       = (const float*)d_in[6];
    const float* W1       = (const float*)d_in[7];
    const float* b1       = (const float*)d_in[8];
    const float* W2       = (const float*)d_in[9];
    const float* b2       = (const float*)d_in[10];
    const float* Wo       = (const float*)d_in[11];
    float* out = (float*)d_out;

    cudaFuncSetAttribute(decoder_kernel,
                         cudaFuncAttributeMaxDynamicSharedMemorySize, SMEM_BYTES);

    decoder_kernel<<<GRID, NTHREADS, SMEM_BYTES>>>(
        memory, feat_idx, emb, Wf, bf, lg, lb, W1, b1, W2, b2, Wo, out);
}

// round 3
// speedup vs baseline: 4.2483x; 4.2483x over previous
#include <cuda_runtime.h>
#include <cuda_fp16.h>
#include <math.h>
#include <stdint.h>

// ---------------- problem constants ----------------
#define NROWS   253952      // B*S*N = 16*512*31
#define DM      256
#define VOC     64
#define NN      31
#define TILE_M  128
#define GRID_M  (NROWS / TILE_M)   // 1984
#define NT      256

// ---------------- smem layout (bytes) ----------------
// X/Y: 128 rows x 264 halfs (528 B pitch, odd 16B multiple -> conflict-free ldmatrix)
#define XPB     528
#define WPB     144           // W chunk: 256 k-rows x 72 halfs (144 B pitch)
#define WCSZ    36864         // 256 * 144
#define SM_X    0
#define SM_Y    67584
#define SM_WC   135168        // two buffers of WCSZ -> ends 208896
#define SM_SG   208896
#define SM_SB   209920
#define SM_BF   210944
#define SM_B1   211968
#define SM_B2   212992
#define SM_ST   214016        // float2[128] = 1024
#define SMEM_BYTES 215040

// ---------------- fp16 weight copies (prep kernel output) ----------------
__device__ __align__(16) __half g_wf[65536];
__device__ __align__(16) __half g_w1[65536];
__device__ __align__(16) __half g_w2[65536];
__device__ __align__(16) __half g_wo[16384];

// ---------------- PTX helpers ----------------
__device__ __forceinline__ uint32_t smem_u32_of(const void* p) {
    uint32_t a;
    asm("{ .reg .u64 t; cvta.to.shared.u64 t, %1; cvt.u32.u64 %0, t; }" : "=r"(a) : "l"(p));
    return a;
}
__device__ __forceinline__ void ldsm_x4(uint32_t* r, uint32_t addr) {
    asm volatile("ldmatrix.sync.aligned.m8n8.x4.shared.b16 {%0,%1,%2,%3}, [%4];"
        : "=r"(r[0]), "=r"(r[1]), "=r"(r[2]), "=r"(r[3]) : "r"(addr));
}
__device__ __forceinline__ void ldsm_x4_t(uint32_t* r, uint32_t addr) {
    asm volatile("ldmatrix.sync.aligned.m8n8.x4.trans.shared.b16 {%0,%1,%2,%3}, [%4];"
        : "=r"(r[0]), "=r"(r[1]), "=r"(r[2]), "=r"(r[3]) : "r"(addr));
}
__device__ __forceinline__ void mma16816(float* d, const uint32_t* a, const uint32_t* b) {
    asm volatile("mma.sync.aligned.m16n8k16.row.col.f32.f16.f16.f32 "
        "{%0,%1,%2,%3}, {%4,%5,%6,%7}, {%8,%9}, {%0,%1,%2,%3};"
        : "+f"(d[0]), "+f"(d[1]), "+f"(d[2]), "+f"(d[3])
        : "r"(a[0]), "r"(a[1]), "r"(a[2]), "r"(a[3]), "r"(b[0]), "r"(b[1]));
}
#define CP_ASYNC16(dst, src) \
    asm volatile("cp.async.cg.shared.global [%0], [%1], 16;" :: "r"(dst), "l"(src) : "memory")
#define CP_COMMIT() asm volatile("cp.async.commit_group;" ::: "memory")
#define CP_WAIT1()  asm volatile("cp.async.wait_group 1;" ::: "memory")
#define CP_WAIT0()  asm volatile("cp.async.wait_group 0;" ::: "memory")

// ---------------- math helpers ----------------
__device__ __forceinline__ float gelu_exact(float x) {
    return 0.5f * x * (1.0f + erff(x * 0.70710678118654752f));
}
__device__ __forceinline__ uint32_t pk(float a, float b) {
    __half2 h = __floats2half2_rn(a, b);
    return *reinterpret_cast<uint32_t*>(&h);
}
__device__ __forceinline__ float2 unpk(uint32_t u) {
    __half2 h = *reinterpret_cast<__half2*>(&u);
    return __half22float2(h);
}

// ---------------- prep: fp32 -> fp16 weights, row-major [k][n] ----------------
__global__ void prep_weights(const float* __restrict__ Wf, const float* __restrict__ W1,
                             const float* __restrict__ W2, const float* __restrict__ Wo) {
    int idx = blockIdx.x * blockDim.x + threadIdx.x;   // 832*256 = 212992
    if (idx < 3 * 65536) {
        int m = idx >> 16, e = idx & 65535;
        const float* W = (m == 0) ? Wf : (m == 1) ? W1 : W2;
        __half* o      = (m == 0) ? g_wf : (m == 1) ? g_w1 : g_w2;
        o[e] = __float2half_rn(W[e]);
    } else {
        int e = idx - 3 * 65536;
        g_wo[e] = __float2half_rn(Wo[e]);
    }
}

// ---------------- weight chunk prefetch (cp.async, double-buffered) ----------------
// chunk c: c in [0,12); c<12 -> W[s= c/4][:, (c&3)*64 .. +64], c==12 -> Wo full.
__device__ __forceinline__ void issue_chunk(uint32_t smb, int tid, int c) {
    const __half* W = (c < 4) ? g_wf : (c < 8) ? g_w1 : (c < 12) ? g_w2 : g_wo;
    int j0 = (c < 12) ? (c & 3) * 64 : 0;
    int gp = (c < 12) ? 256 : 64;                      // global pitch in halfs
    uint32_t dstb = smb + SM_WC + (uint32_t)(c & 1) * WCSZ;
    #pragma unroll
    for (int i = tid; i < 2048; i += NT) {             // 256 rows x 8 x 16B
        int k = i >> 3, c16 = i & 7;
        const uint8_t* src = (const uint8_t*)(W + (size_t)k * gp + j0) + (c16 << 4);
        CP_ASYNC16(dstb + k * WPB + (c16 << 4), src);
    }
    CP_COMMIT();
}

// ---------------- per-warp GEMM chunk: acc[8][4] += A[128x256] @ Wc[256x64] ----------------
__device__ __forceinline__ void gemm_chunk(uint32_t abase, uint32_t wbase,
                                           int r0, int lane, float acc[8][4]) {
    const uint32_t a_addr = abase + (uint32_t)(r0 + (lane & 15)) * XPB + ((lane >> 4) << 4);
    const uint32_t b_addr = wbase + (uint32_t)(lane & 15) * WPB + ((lane >> 4) << 4);
    #pragma unroll 4
    for (int k0 = 0; k0 < 256; k0 += 16) {
        uint32_t a[4];
        ldsm_x4(a, a_addr + k0 * 2);
        #pragma unroll
        for (int t = 0; t < 4; t++) {
            uint32_t b[4];
            ldsm_x4_t(b, b_addr + k0 * WPB + t * 32);
            mma16816(acc[t * 2],     a, b);
            mma16816(acc[t * 2 + 1], a, b + 2);
        }
    }
}

// ---------------- main fused kernel ----------------
__global__ void __launch_bounds__(NT, 1)
dec_main(const float* __restrict__ memory, const int* __restrict__ fidx,
         const float* __restrict__ emb,
         const float* __restrict__ bf, const float* __restrict__ lg,
         const float* __restrict__ lb, const float* __restrict__ b1,
         const float* __restrict__ b2, float* __restrict__ out)
{
    extern __shared__ __align__(16) uint8_t sm[];
    const int tid  = threadIdx.x;
    const int wid  = tid >> 5;
    const int lane = tid & 31;
    const int gr0  = blockIdx.x * TILE_M;
    const uint32_t smb = smem_u32_of(sm);

    float* sg  = (float*)(sm + SM_SG);
    float* sb  = (float*)(sm + SM_SB);
    float* pbf = (float*)(sm + SM_BF);
    float* pb1 = (float*)(sm + SM_B1);
    float* pb2 = (float*)(sm + SM_B2);
    float2* st = (float2*)(sm + SM_ST);

    issue_chunk(smb, tid, 0);   // prefetch first weight chunk ASAP

    // params (one element of each per thread)
    { int i = tid; sg[i] = lg[i]; sb[i] = lb[i]; pbf[i] = bf[i]; pb1[i] = b1[i]; pb2[i] = b2[i]; }

    // gather: X = fp16(emb[feat_idx]) row-major, pitch XPB
    for (int q = tid; q < TILE_M * 8; q += NT) {       // (row, 32-col chunk)
        int row = q >> 3, c32 = (q & 7) << 5;
        int e = __ldg(fidx + gr0 + row);
        const float4* src = (const float4*)(emb + (size_t)e * DM + c32);
        uint4* dst = (uint4*)(sm + SM_X + row * XPB + c32 * 2);
        #pragma unroll
        for (int u = 0; u < 4; u++) {
            float4 f0 = __ldg(src + 2 * u);
            float4 f1 = __ldg(src + 2 * u + 1);
            uint4 p;
            p.x = pk(f0.x, f0.y); p.y = pk(f0.z, f0.w);
            p.z = pk(f1.x, f1.y); p.w = pk(f1.z, f1.w);
            dst[u] = p;
        }
    }

    const int r0  = wid * 16;
    const int rlo = r0 + (lane >> 2);
    const int rhi = rlo + 8;
    const float* mlo = memory + (size_t)((gr0 + rlo) / NN) * DM;
    const float* mhi = memory + (size_t)((gr0 + rhi) / NN) * DM;

    // ---- stages 0..2: GEMM(256x256 by 4 chunks) + bias + gelu (+mem) (+LN) ----
    for (int s = 0; s < 3; s++) {
        const float* bias = (s == 0) ? pbf : (s == 1) ? pb1 : pb2;
        float s1lo = 0.f, s2lo = 0.f, s1hi = 0.f, s2hi = 0.f;

        for (int jc = 0; jc < 4; jc++) {
            const int c = s * 4 + jc;
            issue_chunk(smb, tid, c + 1);
            CP_WAIT1();
            __syncthreads();   // Wc[c&1] ready; also orders gather/LN writes vs reads

            float acc[8][4] = {};
            gemm_chunk(smb + SM_X, smb + SM_WC + (uint32_t)(c & 1) * WCSZ, r0, lane, acc);

            const int j0 = jc * 64;
            #pragma unroll
            for (int t = 0; t < 8; t++) {
                const int col = j0 + t * 8 + ((lane & 3) << 1);
                float x0 = gelu_exact(acc[t][0] + bias[col]);
                float x1 = gelu_exact(acc[t][1] + bias[col + 1]);
                float x2 = gelu_exact(acc[t][2] + bias[col]);
                float x3 = gelu_exact(acc[t][3] + bias[col + 1]);
                if (s == 0) {
                    float2 m0 = *(const float2*)(mlo + col);
                    float2 m1 = *(const float2*)(mhi + col);
                    x0 += m0.x; x1 += m0.y; x2 += m1.x; x3 += m1.y;
                }
                s1lo += x0 + x1; s2lo += x0 * x0 + x1 * x1;
                s1hi += x2 + x3; s2hi += x2 * x2 + x3 * x3;
                *(uint32_t*)(sm + SM_Y + rlo * XPB + col * 2) = pk(x0, x1);
                *(uint32_t*)(sm + SM_Y + rhi * XPB + col * 2) = pk(x2, x3);
            }
        }

        if (s < 2) {
            // row stats: reduce across the quad (lanes sharing a row)
            #pragma unroll
            for (int off = 1; off <= 2; off <<= 1) {
                s1lo += __shfl_xor_sync(0xffffffffu, s1lo, off);
                s2lo += __shfl_xor_sync(0xffffffffu, s2lo, off);
                s1hi += __shfl_xor_sync(0xffffffffu, s1hi, off);
                s2hi += __shfl_xor_sync(0xffffffffu, s2hi, off);
            }
            if ((lane & 3) == 0) {
                st[rlo] = make_float2(s1lo, s2lo);
                st[rhi] = make_float2(s1hi, s2hi);
            }
            __syncthreads();   // Y + st complete

            // LN: X[row] = (Y[row]-mu)*rs*g + b   (2 threads per row, 128 cols each)
            const int row = tid >> 1, ch = tid & 1;
            float2 t2 = st[row];
            const float mu  = t2.x * (1.0f / 256.0f);
            const float var = t2.y * (1.0f / 256.0f) - mu * mu;
            const float rs  = rsqrtf(var + 1e-5f);
            #pragma unroll
            for (int u = 0; u < 16; u++) {
                const int cb = ch * 128 + u * 8;
                uint4 p = *(uint4*)(sm + SM_Y + row * XPB + cb * 2);
                uint32_t* pw = &p.x;
                #pragma unroll
                for (int w = 0; w < 4; w++) {
                    float2 f = unpk(pw[w]);
                    const int cc = cb + 2 * w;
                    f.x = (f.x - mu) * rs * sg[cc]     + sb[cc];
                    f.y = (f.y - mu) * rs * sg[cc + 1] + sb[cc + 1];
                    pw[w] = pk(f.x, f.y);
                }
                *(uint4*)(sm + SM_X + row * XPB + cb * 2) = p;
            }
            // next chunk's __syncthreads orders these writes before reads
        }
    }

    // ---- stage 3: logits = Y @ Wo (N=64), then softmax ----
    CP_WAIT0();
    __syncthreads();           // Wc[0] (chunk 12) ready; Y (stage-2 out) complete

    float acc[8][4] = {};
    gemm_chunk(smb + SM_Y, smb + SM_WC, r0, lane, acc);

    // softmax within the quad (4 lanes x 16 cols per row)
    float mxlo = acc[0][0], mxhi = acc[0][2];
    #pragma unroll
    for (int t = 0; t < 8; t++) {
        mxlo = fmaxf(mxlo, fmaxf(acc[t][0], acc[t][1]));
        mxhi = fmaxf(mxhi, fmaxf(acc[t][2], acc[t][3]));
    }
    #pragma unroll
    for (int off = 1; off <= 2; off <<= 1) {
        mxlo = fmaxf(mxlo, __shfl_xor_sync(0xffffffffu, mxlo, off));
        mxhi = fmaxf(mxhi, __shfl_xor_sync(0xffffffffu, mxhi, off));
    }
    float smlo = 0.f, smhi = 0.f;
    #pragma unroll
    for (int t = 0; t < 8; t++) {
        acc[t][0] = expf(acc[t][0] - mxlo); smlo += acc[t][0];
        acc[t][1] = expf(acc[t][1] - mxlo); smlo += acc[t][1];
        acc[t][2] = expf(acc[t][2] - mxhi); smhi += acc[t][2];
        acc[t][3] = expf(acc[t][3] - mxhi); smhi += acc[t][3];
    }
    #pragma unroll
    for (int off = 1; off <= 2; off <<= 1) {
        smlo += __shfl_xor_sync(0xffffffffu, smlo, off);
        smhi += __shfl_xor_sync(0xffffffffu, smhi, off);
    }
    const float ilo = 1.0f / smlo, ihi = 1.0f / smhi;

    // stage probs (fp32, [128][64]) into the free Wc buffer, then coalesced store
    float* pr = (float*)(sm + SM_WC + WCSZ);
    #pragma unroll
    for (int t = 0; t < 8; t++) {
        const int col = t * 8 + ((lane & 3) << 1);
        *(float2*)(pr + rlo * VOC + col) = make_float2(acc[t][0] * ilo, acc[t][1] * ilo);
        *(float2*)(pr + rhi * VOC + col) = make_float2(acc[t][2] * ihi, acc[t][3] * ihi);
    }
    __syncthreads();

    float4* og = (float4*)(out + (size_t)gr0 * VOC);
    const float4* ps = (const float4*)pr;
    #pragma unroll
    for (int i = tid; i < TILE_M * VOC / 4; i += NT)   // 2048 float4
        og[i] = ps[i];
}

// ---------------- harness entry ----------------
extern "C" void kernel_launch(void* const* d_in, const int* in_sizes, int n_in,
                              void* d_out, int out_size)
{
    const float* memory   = (const float*)d_in[0];
    const int*   feat_idx = (const int*)  d_in[1];
    const float* emb      = (const float*)d_in[2];
    const float* Wf       = (const float*)d_in[3];
    const float* bf       = (const float*)d_in[4];
    const float* lg       = (const float*)d_in[5];
    const float* lb       = (const float*)d_in[6];
    const float* W1       = (const float*)d_in[7];
    const float* b1       = (const float*)d_in[8];
    const float* W2       = (const float*)d_in[9];
    const float* b2       = (const float*)d_in[10];
    const float* Wo       = (const float*)d_in[11];
    float* out = (float*)d_out;

    cudaFuncSetAttribute(dec_main, cudaFuncAttributeMaxDynamicSharedMemorySize, SMEM_BYTES);

    prep_weights<<<832, 256>>>(Wf, W1, W2, Wo);
    dec_main<<<GRID_M, NT, SMEM_BYTES>>>(memory, feat_idx, emb, bf, lg, lb, b1, b2, out);
}